// round 15
// baseline (speedup 1.0000x reference)
#include <cuda_runtime.h>
#include <cuda_fp16.h>

// out[b,l,g,o] = sum_k mask(b,l,k) * sum_i X[b,l+k-2,g*64+i] * W[g,o,i,k]
// mask(l,k) = (pos[l+k-2]-(l+k-2) == pos[l]-l); X zero-padded outside [0,L).
// Single-pass fp16 (X,W rounded once), fp32 accumulate. rel_err ~3e-4.
// W pre-arranged in mma-fragment order; staged once per CTA into smem.
// Warp tile M=32 x N=32; A and B software-pipelined at distance 1.
// Mask applied via ldmatrix ADDRESS redirection to a zero chunk (no data selps).
// 256 thr/CTA (8 warps: 4 M-tiles x 2 N-halves), 3 CTAs/SM (24 warps/SM).

constexpr int Bb = 4, Ll = 4096, Cc = 1024, Gg = 16, IPG = 64, OPG = 64, KK = 5, TL = 128;
constexpr int A_ROWS = TL + 4;    // 132

// W in fragment order: uint = 2 halfs; index = ((((g*5+k)*4+q)*4+p)*32+L)*4+j
__device__ unsigned g_Wfrag[Gg * KK * 4 * 4 * 32 * 4];

// smem layout (bytes)
constexpr int SA   = 0;                        // A: 132 x 128B swizzled rows
constexpr int SW_F = A_ROWS * 128;             // 16896: W frags, 2560 x 16B linear
constexpr int W_BYTES = KK * 4 * 4 * 32 * 16;  // 40960
constexpr int S_DQ = SW_F + W_BYTES;           // 57856: dq, 132 ints
constexpr int S_ZERO = S_DQ + 544;             // 16B zero chunk (ldsm mask target)
constexpr int SMEM_BYTES = S_ZERO + 16;        // ~58.4 KB -> 3 CTAs/SM

__device__ __forceinline__ unsigned smem_u32(const void* p) {
    unsigned a;
    asm("{ .reg .u64 t; cvta.to.shared.u64 t, %1; cvt.u32.u64 %0, t; }" : "=r"(a) : "l"(p));
    return a;
}
__device__ __forceinline__ unsigned sw128(unsigned off) { return off ^ ((off >> 3) & 0x70); }

__device__ __forceinline__ void sts64(unsigned addr, unsigned r0, unsigned r1) {
    asm volatile("st.shared.v2.b32 [%0], {%1, %2};" :: "r"(addr), "r"(r0), "r"(r1) : "memory");
}
__device__ __forceinline__ void ldsm4(unsigned addr, unsigned& r0, unsigned& r1,
                                      unsigned& r2, unsigned& r3) {
    asm volatile("ldmatrix.sync.aligned.m8n8.x4.shared.b16 {%0, %1, %2, %3}, [%4];"
                 : "=r"(r0), "=r"(r1), "=r"(r2), "=r"(r3) : "r"(addr));
}
__device__ __forceinline__ void lds128(unsigned addr, unsigned& r0, unsigned& r1,
                                       unsigned& r2, unsigned& r3) {
    asm volatile("ld.shared.v4.b32 {%0, %1, %2, %3}, [%4];"
                 : "=r"(r0), "=r"(r1), "=r"(r2), "=r"(r3) : "r"(addr));
}
__device__ __forceinline__ void mma16816(float* c,
                                         unsigned a0, unsigned a1, unsigned a2, unsigned a3,
                                         unsigned b0, unsigned b1) {
    asm volatile("mma.sync.aligned.m16n8k16.row.col.f32.f16.f16.f32 "
                 "{%0,%1,%2,%3}, {%4,%5,%6,%7}, {%8,%9}, {%0,%1,%2,%3};"
                 : "+f"(c[0]), "+f"(c[1]), "+f"(c[2]), "+f"(c[3])
                 : "r"(a0), "r"(a1), "r"(a2), "r"(a3), "r"(b0), "r"(b1));
}
__device__ __forceinline__ void cp16(unsigned dst, const void* src) {
    asm volatile("cp.async.cg.shared.global [%0], [%1], 16;" :: "r"(dst), "l"(src) : "memory");
}

// ---- pre-kernel: W (g,o,i,k) f32 -> fragment-ordered fp16 pairs ----
// One block per g. Coalesced LDG -> smem (fp16, original layout) -> coalesced
// frag-ordered STG (the scatter happens in cheap LDS reads).
// reg j of lane L, tile (k,q,p):  o = p*16 + 8*(j>>1) + (L>>2)
//                                 i = q*16 + 8*(j&1) + 2*(L&3)   (+1 for hi half)
__global__ void prep_w(const float* __restrict__ w) {
    __shared__ __half ws[KK * OPG * IPG];      // 20480 halfs = 40 KB
    const int g = blockIdx.x;
    const int tid = threadIdx.x;
    const float* wg = w + (size_t)g * (KK * OPG * IPG);
#pragma unroll
    for (int t = 0; t < 80; t++) {             // 20480 / 256
        int idx = tid + t * 256;               // (o*IPG + i)*KK + k linear
        ws[idx] = __float2half_rn(wg[idx]);
    }
    __syncthreads();
    unsigned* dst = g_Wfrag + (size_t)g * (KK * 4 * 4 * 32 * 4);
#pragma unroll
    for (int t = 0; t < 40; t++) {             // 10240 / 256
        int d = tid + t * 256;
        int j = d & 3;
        int L = (d >> 2) & 31;
        int p = (d >> 7) & 3;
        int q = (d >> 9) & 3;
        int k = d >> 11;
        int o = p * 16 + ((j >> 1) << 3) + (L >> 2);
        int i = q * 16 + ((j & 1) << 3) + ((L & 3) << 1);
        __half h0 = ws[(o * IPG + i) * KK + k];
        __half h1 = ws[(o * IPG + i + 1) * KK + k];
        __half2 pk = __halves2half2(h0, h1);
        dst[d] = *reinterpret_cast<unsigned*>(&pk);
    }
}

__global__ __launch_bounds__(256, 3)
void masked_conv1d_hmma(const float* __restrict__ x,
                        const int*   __restrict__ pos,
                        float*       __restrict__ out) {
    extern __shared__ char sm[];
    const unsigned smb = smem_u32(sm);
    const int l0 = blockIdx.x * TL, g = blockIdx.y, b = blockIdx.z;
    const int tid = threadIdx.x;
    const int wid = tid >> 5, lane = tid & 31;
    const int lane8 = lane & 7, seg = lane >> 3;

    // ---- stage ALL W fragments for this g into smem (2560 x 16B chunks) ----
    {
        const char* wsrc = (const char*)((const uint4*)g_Wfrag + (size_t)g * (KK * 16 * 32));
#pragma unroll
        for (int t = 0; t < 10; t++) {
            int ch = tid + t * 256;
            cp16(smb + SW_F + (unsigned)ch * 16, wsrc + (size_t)ch * 16);
        }
        asm volatile("cp.async.commit_group;" ::: "memory");
    }

    // ---- stage position deltas into smem (coalesced) + 16B zero chunk ----
    int* dq = (int*)(sm + S_DQ);
    for (int j = tid; j < A_ROWS; j += 256) {
        int gl = l0 - 2 + j;
        dq[j] = (gl >= 0 && gl < Ll) ? (pos[b * Ll + gl] - gl) : (int)0x80000000 + j;
    }
    if (tid < 4) ((unsigned*)(sm + S_ZERO))[tid] = 0u;

    // ---- stage X tile: f32 -> fp16, swizzled 128B rows ----
    const float* xg = x + (size_t)b * Ll * Cc + g * IPG;
    for (int idx = tid; idx < A_ROWS * 16; idx += 256) {
        int j  = idx >> 4;
        int i4 = idx & 15;
        int gl = l0 - 2 + j;
        float4 v = make_float4(0.f, 0.f, 0.f, 0.f);
        if (gl >= 0 && gl < Ll)
            v = *(const float4*)(xg + (size_t)gl * Cc + i4 * 4);
        unsigned h0, h1;
        asm("cvt.rn.f16x2.f32 %0, %1, %2;" : "=r"(h0) : "f"(v.y), "f"(v.x));
        asm("cvt.rn.f16x2.f32 %0, %1, %2;" : "=r"(h1) : "f"(v.w), "f"(v.z));
        unsigned sw = sw128((unsigned)(j * 128 + i4 * 8));
        sts64(smb + SA + sw, h0, h1);
    }

    asm volatile("cp.async.wait_group 0;" ::: "memory");
    __syncthreads();                                  // A + dq + W + zero visible; the ONLY barrier

    const int mw = wid >> 1;          // 0..3: M-tile (32 rows)
    const int nw = wid & 1;           // 0..1: N-half (32 cols)

    // ---- per-lane ldsm-row masks: this lane supplies rows R_a0 (a0) and R_a0+16 (a1) ----
    // bit k of mk0/mk1 = mask(row, tap k); bit 2 is always 1 (center tap).
    const int R_a0 = mw * 32 + lane8 + ((seg & 1) << 3);
    unsigned mk0 = 0, mk1 = 0;
    {
        int c0 = dq[R_a0 + 2], c1 = dq[R_a0 + 16 + 2];
#pragma unroll
        for (int k = 0; k < KK; k++) {
            if (dq[R_a0 + k] == c0)      mk0 |= 1u << k;
            if (dq[R_a0 + 16 + k] == c1) mk1 |= 1u << k;
        }
    }
    const unsigned za = smb + S_ZERO;

    // ---- accumulators: [mt 0..1][nt 0..3][e 0..3] ----
    float c[2][4][4];
#pragma unroll
    for (int mt = 0; mt < 2; mt++)
#pragma unroll
        for (int nt = 0; nt < 4; nt++)
#pragma unroll
            for (int e = 0; e < 4; e++) c[mt][nt][e] = 0.f;

    const unsigned acoff = (unsigned)((seg >> 1) << 3);
    // per-lane W base for this warp's N-half
    const unsigned wbase = smb + SW_F + (unsigned)(nw * 2) * 512 + (unsigned)lane * 16;

    // ---- prologue: prefetch A (mask-redirected) and B for it=0 ----
    unsigned bc[8], ah[8];
    lds128(wbase,       bc[0], bc[1], bc[2], bc[3]);
    lds128(wbase + 512, bc[4], bc[5], bc[6], bc[7]);
    {
        const unsigned arow = (unsigned)(mw * 32 + 0 + lane8 + ((seg & 1) << 3));
        unsigned a0 = smb + SA + sw128(arow * 128 + (0 * 16 + acoff) * 2);
        unsigned a1 = smb + SA + sw128((arow + 16) * 128 + (0 * 16 + acoff) * 2);
        a0 = (mk0 & 1u) ? a0 : za;
        a1 = (mk1 & 1u) ? a1 : za;
        ldsm4(a0, ah[0], ah[1], ah[2], ah[3]);
        ldsm4(a1, ah[4], ah[5], ah[6], ah[7]);
    }

#pragma unroll
    for (int it = 0; it < 20; it++) {
        // prefetch A (mask-redirected) and B for it+1 while MMAs of it run
        unsigned bn[8], an[8];
        if (it < 19) {
            unsigned wn = wbase + (unsigned)(it + 1) * 2048;
            lds128(wn,       bn[0], bn[1], bn[2], bn[3]);
            lds128(wn + 512, bn[4], bn[5], bn[6], bn[7]);
            const int kn = (it + 1) >> 2, qn = (it + 1) & 3;
            const unsigned arown = (unsigned)(mw * 32 + kn + lane8 + ((seg & 1) << 3));
            unsigned a0 = smb + SA + sw128(arown * 128 + (qn * 16 + acoff) * 2);
            unsigned a1 = smb + SA + sw128((arown + 16) * 128 + (qn * 16 + acoff) * 2);
            a0 = ((mk0 >> kn) & 1u) ? a0 : za;
            a1 = ((mk1 >> kn) & 1u) ? a1 : za;
            ldsm4(a0, an[0], an[1], an[2], an[3]);
            ldsm4(a1, an[4], an[5], an[6], an[7]);
        }

#pragma unroll
        for (int mt = 0; mt < 2; mt++) {
            mma16816(c[mt][0], ah[mt*4], ah[mt*4+1], ah[mt*4+2], ah[mt*4+3], bc[0], bc[1]);
            mma16816(c[mt][1], ah[mt*4], ah[mt*4+1], ah[mt*4+2], ah[mt*4+3], bc[2], bc[3]);
            mma16816(c[mt][2], ah[mt*4], ah[mt*4+1], ah[mt*4+2], ah[mt*4+3], bc[4], bc[5]);
            mma16816(c[mt][3], ah[mt*4], ah[mt*4+1], ah[mt*4+2], ah[mt*4+3], bc[6], bc[7]);
        }

#pragma unroll
        for (int j = 0; j < 8; j++) { bc[j] = bn[j]; ah[j] = an[j]; }
    }

    // ---- epilogue: fragments -> out (B,L,G,OPG) ----
    const int ocol = nw * 32 + (lane & 3) * 2;
#pragma unroll
    for (int mt = 0; mt < 2; mt++) {
        const int row0 = l0 + mw * 32 + mt * 16 + (lane >> 2);
        float* o0 = out + (((size_t)b * Ll + row0) * Gg + g) * OPG + ocol;
        float* o1 = o0 + (size_t)8 * Gg * OPG;
#pragma unroll
        for (int nt = 0; nt < 4; nt++) {
            *(float2*)(o0 + nt * 8) = make_float2(c[mt][nt][0], c[mt][nt][1]);
            *(float2*)(o1 + nt * 8) = make_float2(c[mt][nt][2], c[mt][nt][3]);
        }
    }
}

extern "C" void kernel_launch(void* const* d_in, const int* in_sizes, int n_in,
                              void* d_out, int out_size) {
    const float* x   = (const float*)d_in[0];
    const int*   pos = (const int*)d_in[1];
    const float* w   = (const float*)d_in[2];
    float*       out = (float*)d_out;

    prep_w<<<Gg, 256>>>(w);

    cudaFuncSetAttribute(masked_conv1d_hmma,
                         cudaFuncAttributeMaxDynamicSharedMemorySize, SMEM_BYTES);
    dim3 grid(Ll / TL, Gg, Bb);   // (32, 16, 4)
    masked_conv1d_hmma<<<grid, 256, SMEM_BYTES>>>(x, pos, out);
}

// round 16
// speedup vs baseline: 1.1074x; 1.1074x over previous
#include <cuda_runtime.h>
#include <cuda_fp16.h>

// out[b,l,g,o] = sum_k mask(b,l,k) * sum_i X[b,l+k-2,g*64+i] * W[g,o,i,k]
// mask(l,k) = (pos[l+k-2]-(l+k-2) == pos[l]-l); X zero-padded outside [0,L).
// Single-pass fp16 (X,W rounded once), fp32 accumulate. rel_err ~3e-4.
// W pre-arranged in mma-fragment order; staged once per CTA into smem.
// Warp tile M=32 x N=32; A and B pipelined at distance 1 via PARITY buffers
// (no register-rotation movs). 256 thr/CTA, 3 CTAs/SM (24 warps/SM).

constexpr int Bb = 4, Ll = 4096, Cc = 1024, Gg = 16, IPG = 64, OPG = 64, KK = 5, TL = 128;
constexpr int A_ROWS = TL + 4;    // 132

// W in fragment order: uint = 2 halfs; index = ((((g*5+k)*4+q)*4+p)*32+L)*4+j
__device__ unsigned g_Wfrag[Gg * KK * 4 * 4 * 32 * 4];

// smem layout (bytes)
constexpr int SA   = 0;                        // A: 132 x 128B swizzled rows
constexpr int SW_F = A_ROWS * 128;             // 16896: W frags, 2560 x 16B linear
constexpr int W_BYTES = KK * 4 * 4 * 32 * 16;  // 40960
constexpr int S_DQ = SW_F + W_BYTES;           // 57856: dq, 132 ints
constexpr int SMEM_BYTES = S_DQ + A_ROWS * 4 + 16;   // ~58.4 KB -> 3 CTAs/SM

__device__ __forceinline__ unsigned smem_u32(const void* p) {
    unsigned a;
    asm("{ .reg .u64 t; cvta.to.shared.u64 t, %1; cvt.u32.u64 %0, t; }" : "=r"(a) : "l"(p));
    return a;
}
__device__ __forceinline__ unsigned sw128(unsigned off) { return off ^ ((off >> 3) & 0x70); }

__device__ __forceinline__ void sts64(unsigned addr, unsigned r0, unsigned r1) {
    asm volatile("st.shared.v2.b32 [%0], {%1, %2};" :: "r"(addr), "r"(r0), "r"(r1) : "memory");
}
__device__ __forceinline__ void ldsm4(unsigned addr, unsigned& r0, unsigned& r1,
                                      unsigned& r2, unsigned& r3) {
    asm volatile("ldmatrix.sync.aligned.m8n8.x4.shared.b16 {%0, %1, %2, %3}, [%4];"
                 : "=r"(r0), "=r"(r1), "=r"(r2), "=r"(r3) : "r"(addr));
}
__device__ __forceinline__ void lds128(unsigned addr, unsigned& r0, unsigned& r1,
                                       unsigned& r2, unsigned& r3) {
    asm volatile("ld.shared.v4.b32 {%0, %1, %2, %3}, [%4];"
                 : "=r"(r0), "=r"(r1), "=r"(r2), "=r"(r3) : "r"(addr));
}
__device__ __forceinline__ void mma16816(float* c,
                                         unsigned a0, unsigned a1, unsigned a2, unsigned a3,
                                         unsigned b0, unsigned b1) {
    asm volatile("mma.sync.aligned.m16n8k16.row.col.f32.f16.f16.f32 "
                 "{%0,%1,%2,%3}, {%4,%5,%6,%7}, {%8,%9}, {%0,%1,%2,%3};"
                 : "+f"(c[0]), "+f"(c[1]), "+f"(c[2]), "+f"(c[3])
                 : "r"(a0), "r"(a1), "r"(a2), "r"(a3), "r"(b0), "r"(b1));
}
__device__ __forceinline__ void cp16(unsigned dst, const void* src) {
    asm volatile("cp.async.cg.shared.global [%0], [%1], 16;" :: "r"(dst), "l"(src) : "memory");
}

// ---- pre-kernel: W (g,o,i,k) f32 -> fragment-ordered fp16 pairs ----
// reg j of lane L, tile (k,q,p):  o = p*16 + 8*(j>>1) + (L>>2)
//                                 i = q*16 + 8*(j&1) + 2*(L&3)   (+1 for hi half)
__global__ void prep_w(const float* __restrict__ w) {
    int idx = blockIdx.x * 256 + threadIdx.x;
    if (idx >= Gg * KK * 4 * 4 * 32 * 4) return;
    int j = idx & 3;
    int L = (idx >> 2) & 31;
    int p = (idx >> 7) & 3;
    int q = (idx >> 9) & 3;
    int rem = idx >> 11;
    int k = rem % KK;
    int g = rem / KK;
    int o = p * 16 + ((j >> 1) << 3) + (L >> 2);
    int i = q * 16 + ((j & 1) << 3) + ((L & 3) << 1);
    float v0 = w[(((g * OPG + o) * IPG + i) * KK) + k];
    float v1 = w[(((g * OPG + o) * IPG + i + 1) * KK) + k];
    unsigned pk;
    asm("cvt.rn.f16x2.f32 %0, %1, %2;" : "=r"(pk) : "f"(v1), "f"(v0));
    g_Wfrag[idx] = pk;
}

__global__ __launch_bounds__(256, 3)
void masked_conv1d_hmma(const float* __restrict__ x,
                        const int*   __restrict__ pos,
                        float*       __restrict__ out) {
    extern __shared__ char sm[];
    const unsigned smb = smem_u32(sm);
    const int l0 = blockIdx.x * TL, g = blockIdx.y, b = blockIdx.z;
    const int tid = threadIdx.x;
    const int wid = tid >> 5, lane = tid & 31;
    const int lane8 = lane & 7, seg = lane >> 3;

    // ---- stage ALL W fragments for this g into smem (2560 x 16B chunks) ----
    {
        const char* wsrc = (const char*)((const uint4*)g_Wfrag + (size_t)g * (KK * 16 * 32));
#pragma unroll
        for (int t = 0; t < 10; t++) {
            int ch = tid + t * 256;
            cp16(smb + SW_F + (unsigned)ch * 16, wsrc + (size_t)ch * 16);
        }
        asm volatile("cp.async.commit_group;" ::: "memory");
    }

    // ---- stage position deltas into smem (coalesced) ----
    int* dq = (int*)(sm + S_DQ);
    for (int j = tid; j < A_ROWS; j += 256) {
        int gl = l0 - 2 + j;
        dq[j] = (gl >= 0 && gl < Ll) ? (pos[b * Ll + gl] - gl) : (int)0x80000000 + j;
    }

    // ---- stage X tile: f32 -> fp16, swizzled 128B rows ----
    const float* xg = x + (size_t)b * Ll * Cc + g * IPG;
    for (int idx = tid; idx < A_ROWS * 16; idx += 256) {
        int j  = idx >> 4;
        int i4 = idx & 15;
        int gl = l0 - 2 + j;
        float4 v = make_float4(0.f, 0.f, 0.f, 0.f);
        if (gl >= 0 && gl < Ll)
            v = *(const float4*)(xg + (size_t)gl * Cc + i4 * 4);
        unsigned h0, h1;
        asm("cvt.rn.f16x2.f32 %0, %1, %2;" : "=r"(h0) : "f"(v.y), "f"(v.x));
        asm("cvt.rn.f16x2.f32 %0, %1, %2;" : "=r"(h1) : "f"(v.w), "f"(v.z));
        unsigned sw = sw128((unsigned)(j * 128 + i4 * 8));
        sts64(smb + SA + sw, h0, h1);
    }

    asm volatile("cp.async.wait_group 0;" ::: "memory");
    __syncthreads();                                  // A + dq + W visible; the ONLY barrier

    const int mw = wid >> 1;          // 0..3: M-tile (32 rows)
    const int nw = wid & 1;           // 0..1: N-half (32 cols)
    const int r0 = mw * 32 + (lane >> 2);

    // ---- per-thread mask bits: bit(ci*5+k) = mask(row r0+ci*8, conv-k) ----
    unsigned mbits = 0;
#pragma unroll
    for (int ci = 0; ci < 4; ci++) {
        int cc = dq[r0 + ci * 8 + 2];
#pragma unroll
        for (int k = 0; k < KK; k++) {
            if (k == 2) continue;                     // mask(l,2) == 1 always
            if (dq[r0 + ci * 8 + k] == cc) mbits |= 1u << (ci * 5 + k);
        }
    }

    // ---- accumulators: [mt 0..1][nt 0..3][e 0..3] ----
    float c[2][4][4];
#pragma unroll
    for (int mt = 0; mt < 2; mt++)
#pragma unroll
        for (int nt = 0; nt < 4; nt++)
#pragma unroll
            for (int e = 0; e < 4; e++) c[mt][nt][e] = 0.f;

    const unsigned acoff = (unsigned)((seg >> 1) << 3);
    // per-lane W base for this warp's N-half
    const unsigned wbase = smb + SW_F + (unsigned)(nw * 2) * 512 + (unsigned)lane * 16;

    // ---- parity-buffered fragments (no rotation movs; it is compile-time) ----
    unsigned ar[2][8], br[2][8];
    lds128(wbase,       br[0][0], br[0][1], br[0][2], br[0][3]);
    lds128(wbase + 512, br[0][4], br[0][5], br[0][6], br[0][7]);
    {
        const unsigned arow = (unsigned)(mw * 32 + 0 + lane8 + ((seg & 1) << 3));
        unsigned a0 = smb + SA + sw128(arow * 128 + (0 * 16 + acoff) * 2);
        unsigned a1 = smb + SA + sw128((arow + 16) * 128 + (0 * 16 + acoff) * 2);
        ldsm4(a0, ar[0][0], ar[0][1], ar[0][2], ar[0][3]);
        ldsm4(a1, ar[0][4], ar[0][5], ar[0][6], ar[0][7]);
    }

#pragma unroll
    for (int it = 0; it < 20; it++) {
        const int cur = it & 1, nxt = cur ^ 1;
        const int k = it >> 2;

        // prefetch A and B for it+1 into the other parity buffer
        if (it < 19) {
            unsigned wn = wbase + (unsigned)(it + 1) * 2048;
            lds128(wn,       br[nxt][0], br[nxt][1], br[nxt][2], br[nxt][3]);
            lds128(wn + 512, br[nxt][4], br[nxt][5], br[nxt][6], br[nxt][7]);
            const int kn = (it + 1) >> 2, qn = (it + 1) & 3;
            const unsigned arown = (unsigned)(mw * 32 + kn + lane8 + ((seg & 1) << 3));
            unsigned a0 = smb + SA + sw128(arown * 128 + (qn * 16 + acoff) * 2);
            unsigned a1 = smb + SA + sw128((arown + 16) * 128 + (qn * 16 + acoff) * 2);
            ldsm4(a0, ar[nxt][0], ar[nxt][1], ar[nxt][2], ar[nxt][3]);
            ldsm4(a1, ar[nxt][4], ar[nxt][5], ar[nxt][6], ar[nxt][7]);
        }

        // row-granular mask on current A fragments (loaded a full iteration ago)
        if (k != 2) {
            const bool m0 = (mbits >> (0 * 5 + k)) & 1;
            const bool m1 = (mbits >> (1 * 5 + k)) & 1;
            const bool m2 = (mbits >> (2 * 5 + k)) & 1;
            const bool m3 = (mbits >> (3 * 5 + k)) & 1;
            ar[cur][0] = m0 ? ar[cur][0] : 0u;  ar[cur][2] = m0 ? ar[cur][2] : 0u;
            ar[cur][1] = m1 ? ar[cur][1] : 0u;  ar[cur][3] = m1 ? ar[cur][3] : 0u;
            ar[cur][4] = m2 ? ar[cur][4] : 0u;  ar[cur][6] = m2 ? ar[cur][6] : 0u;
            ar[cur][5] = m3 ? ar[cur][5] : 0u;  ar[cur][7] = m3 ? ar[cur][7] : 0u;
        }

#pragma unroll
        for (int mt = 0; mt < 2; mt++) {
            mma16816(c[mt][0], ar[cur][mt*4], ar[cur][mt*4+1], ar[cur][mt*4+2], ar[cur][mt*4+3],
                     br[cur][0], br[cur][1]);
            mma16816(c[mt][1], ar[cur][mt*4], ar[cur][mt*4+1], ar[cur][mt*4+2], ar[cur][mt*4+3],
                     br[cur][2], br[cur][3]);
            mma16816(c[mt][2], ar[cur][mt*4], ar[cur][mt*4+1], ar[cur][mt*4+2], ar[cur][mt*4+3],
                     br[cur][4], br[cur][5]);
            mma16816(c[mt][3], ar[cur][mt*4], ar[cur][mt*4+1], ar[cur][mt*4+2], ar[cur][mt*4+3],
                     br[cur][6], br[cur][7]);
        }
    }

    // ---- epilogue: fragments -> out (B,L,G,OPG) ----
    const int ocol = nw * 32 + (lane & 3) * 2;
#pragma unroll
    for (int mt = 0; mt < 2; mt++) {
        const int row0 = l0 + mw * 32 + mt * 16 + (lane >> 2);
        float* o0 = out + (((size_t)b * Ll + row0) * Gg + g) * OPG + ocol;
        float* o1 = o0 + (size_t)8 * Gg * OPG;
#pragma unroll
        for (int nt = 0; nt < 4; nt++) {
            *(float2*)(o0 + nt * 8) = make_float2(c[mt][nt][0], c[mt][nt][1]);
            *(float2*)(o1 + nt * 8) = make_float2(c[mt][nt][2], c[mt][nt][3]);
        }
    }
}

extern "C" void kernel_launch(void* const* d_in, const int* in_sizes, int n_in,
                              void* d_out, int out_size) {
    const float* x   = (const float*)d_in[0];
    const int*   pos = (const int*)d_in[1];
    const float* w   = (const float*)d_in[2];
    float*       out = (float*)d_out;

    prep_w<<<(Gg * KK * 4 * 4 * 32 * 4 + 255) / 256, 256>>>(w);

    cudaFuncSetAttribute(masked_conv1d_hmma,
                         cudaFuncAttributeMaxDynamicSharedMemorySize, SMEM_BYTES);
    dim3 grid(Ll / TL, Gg, Bb);   // (32, 16, 4)
    masked_conv1d_hmma<<<grid, 256, SMEM_BYTES>>>(x, pos, out);
}